// round 6
// baseline (speedup 1.0000x reference)
#include <cuda_runtime.h>
#include <cuda_bf16.h>

#define Bb 8
#define Nn 4096
#define Dd 64
#define Gg 32
#define Kk 16

typedef unsigned long long ull;

// scratch
__device__ int g_nbr[Bb * Nn * Kk];
__device__ float g_W1p[64 * 256];   // W1[0:64] - W1[128:192]   (x part)
__device__ float g_W1n[64 * 256];   // W1[64:128] + W1[128:192] (nbr part)

// ---------------------------------------------------------------------------
// f32x2 packed helpers
// ---------------------------------------------------------------------------
__device__ __forceinline__ ull pack2(float a, float b) {
    ull r;
    asm("mov.b64 %0, {%1, %2};" : "=l"(r) : "f"(a), "f"(b));
    return r;
}
__device__ __forceinline__ ull fma2(ull a, ull b, ull c) {
    ull d;
    asm("fma.rn.f32x2 %0, %1, %2, %3;" : "=l"(d) : "l"(a), "l"(b), "l"(c));
    return d;
}
__device__ __forceinline__ ull add2(ull a, ull b) {
    ull d;
    asm("add.rn.f32x2 %0, %1, %2;" : "=l"(d) : "l"(a), "l"(b));
    return d;
}
__device__ __forceinline__ ull mul2(ull a, ull b) {
    ull d;
    asm("mul.rn.f32x2 %0, %1, %2;" : "=l"(d) : "l"(a), "l"(b));
    return d;
}
__device__ __forceinline__ float2 unpack2(ull v) {
    float2 f;
    asm("mov.b64 {%0, %1}, %2;" : "=f"(f.x), "=f"(f.y) : "l"(v));
    return f;
}

// ---------------------------------------------------------------------------
// Kernel 1: KNN (blocks 0..255, f32x2-packed candidate pairs) + W1 fold.
// Distance math is bit-identical to the scalar version:
//   dot  = fma(qx,cx, fma(qy,cy, fma(qz,cz, 0)))  (per lane, same order)
//   dist = fadd(fadd(sqn,sqm), fmul(-2,dot)) == fsub(fadd(sqn,sqm), fmul(2,dot))
// ---------------------------------------------------------------------------
__global__ __launch_bounds__(128) void knn_prep_kernel(const float* __restrict__ pos,
                                                       const float* __restrict__ W1) {
    const int bx = blockIdx.x;
    if (bx >= 256) {
        const int i = (bx - 256) * 128 + threadIdx.x;   // 0..16383
        const int j = i >> 8;
        const int c = i & 255;
        const float wa = W1[j * 256 + c];
        const float wb = W1[(64 + j) * 256 + c];
        const float wc = W1[(128 + j) * 256 + c];
        g_W1p[i] = wa - wc;
        g_W1n[i] = wb + wc;
        return;
    }

    const int b = bx >> 5;
    const int n = ((bx & 31) << 7) + threadIdx.x;

    const float qx = pos[(b * Nn + n) * 3 + 0];
    const float qy = pos[(b * Nn + n) * 3 + 1];
    const float qz = pos[(b * Nn + n) * 3 + 2];
    const float sqn = __fadd_rn(__fadd_rn(__fmul_rn(qx, qx), __fmul_rn(qy, qy)),
                                __fmul_rn(qz, qz));
    const ull qxp = pack2(qx, qx);
    const ull qyp = pack2(qy, qy);
    const ull qzp = pack2(qz, qz);
    const ull sqp = pack2(sqn, sqn);
    const ull n2p = pack2(-2.0f, -2.0f);
    const ull zer = pack2(0.0f, 0.0f);

    float bd[16];
    int bi[16];
#pragma unroll
    for (int j = 0; j < 16; ++j) { bd[j] = 3.0e38f; bi[j] = 0; }
    float worst = 3.0e38f;
    int wslot = 0;

    __shared__ float4 tileA[512];   // (x0, x1, y0, y1) per candidate pair
    __shared__ float4 tileB[512];   // (z0, z1, s0, s1)

    for (int t0 = 0; t0 < Nn; t0 += 1024) {
        __syncthreads();
        const float* pp = pos + (b * Nn + t0) * 3;
        for (int i = threadIdx.x; i < 512; i += 128) {
            const float2 u0 = *(const float2*)(pp + 6 * i);       // x0 y0
            const float2 u1 = *(const float2*)(pp + 6 * i + 2);   // z0 x1
            const float2 u2 = *(const float2*)(pp + 6 * i + 4);   // y1 z1
            const float s0 = __fadd_rn(__fadd_rn(__fmul_rn(u0.x, u0.x),
                                                 __fmul_rn(u0.y, u0.y)),
                                       __fmul_rn(u1.x, u1.x));
            const float s1 = __fadd_rn(__fadd_rn(__fmul_rn(u1.y, u1.y),
                                                 __fmul_rn(u2.x, u2.x)),
                                       __fmul_rn(u2.y, u2.y));
            tileA[i] = make_float4(u0.x, u1.y, u0.y, u2.x);
            tileB[i] = make_float4(u1.x, u2.y, s0, s1);
        }
        __syncthreads();
#pragma unroll 4
        for (int i = 0; i < 512; ++i) {
            const ulonglong2 A = ((const ulonglong2*)tileA)[i];
            const ulonglong2 Bv = ((const ulonglong2*)tileB)[i];
            ull dot2 = fma2(qxp, A.x, zer);
            dot2 = fma2(qyp, A.y, dot2);
            dot2 = fma2(qzp, Bv.x, dot2);
            const ull sum2 = add2(sqp, Bv.y);
            const ull d2 = add2(sum2, mul2(n2p, dot2));
            const float2 d = unpack2(d2);
            const int m0 = t0 + 2 * i;
            if (d.x < worst && m0 != n) {
#pragma unroll
                for (int j = 0; j < 16; ++j)
                    if (j == wslot) { bd[j] = d.x; bi[j] = m0; }
                worst = bd[0]; wslot = 0;
#pragma unroll
                for (int j = 1; j < 16; ++j)
                    if (bd[j] > worst) { worst = bd[j]; wslot = j; }
            }
            if (d.y < worst && (m0 + 1) != n) {
#pragma unroll
                for (int j = 0; j < 16; ++j)
                    if (j == wslot) { bd[j] = d.y; bi[j] = m0 + 1; }
                worst = bd[0]; wslot = 0;
#pragma unroll
                for (int j = 1; j < 16; ++j)
                    if (bd[j] > worst) { worst = bd[j]; wslot = j; }
            }
        }
    }

#pragma unroll
    for (int j = 0; j < 16; ++j)
        g_nbr[(b * Nn + n) * 16 + j] = bi[j];
}

// ---------------------------------------------------------------------------
// Kernel 2: fused DenseEdgeConv. 2 points (32 k-lanes), 128 threads, 3 CTAs/SM.
// ---------------------------------------------------------------------------
#define SROW 36
#define P2 2

#define OFF_NBRT 0
#define OFF_H1   (OFF_NBRT + 64 * SROW)
#define OFF_Y2   (OFF_H1 + 256 * SROW)
#define OFF_XH   (OFF_Y2 + 128 * SROW)
#define OFF_XN   (OFF_XH + P2 * 256)
#define OFF_YBAR (OFF_XN + P2 * 64)
#define OFF_GATE (OFF_YBAR + P2 * 128)
#define OFF_NID  (OFF_GATE + P2 * 128)
#define SMEM_FLOATS (OFF_NID + 32)

__global__ __launch_bounds__(128, 3) void conv_kernel(
    const float* __restrict__ x,
    const float* __restrict__ b1,
    const float* __restrict__ W2, const float* __restrict__ b2,
    const float* __restrict__ Wmid, const float* __restrict__ bmid,
    const float* __restrict__ Wg, const float* __restrict__ bg,
    const float* __restrict__ Wlast, const float* __restrict__ blast,
    float* __restrict__ out)
{
    extern __shared__ float sm[];
    float* sNbrT = sm + OFF_NBRT;   // [64 j][SROW k]
    float* sH1 = sm + OFF_H1;       // [256 c][SROW k]
    float* sY2 = sm + OFF_Y2;       // [128 ch][SROW k]: 0..31 m, 32..63 h, 64..127 xn
    float* sXh = sm + OFF_XH;       // [2 p][256 c]
    float* sXn = sm + OFF_XN;       // [2 p][64 c]
    float* sYbar = sm + OFF_YBAR;   // [2 p][128]
    float* sGate = sm + OFF_GATE;   // [2 p][128]
    int* sNid = (int*)(sm + OFF_NID);

    const int t = threadIdx.x;
    const int g0 = blockIdx.x * P2;
    const int b = g0 >> 12;

    sXn[t] = x[(g0 + (t >> 6)) * 64 + (t & 63)];
    if (t < 32) sNid[t] = g_nbr[g0 * 16 + t];
    __syncthreads();

    // ---- gather neighbor features (transposed, LDG.128) + xn rows of y2 ---
#pragma unroll
    for (int it = 0; it < 4; ++it) {
        const int idx = it * 128 + t;       // 0..511
        const int kk = idx >> 4;            // 0..31
        const int c4 = (idx & 15) << 2;     // 0,4,...,60
        const float4 v = *(const float4*)(x + (b * Nn + sNid[kk]) * 64 + c4);
        sNbrT[(c4 + 0) * SROW + kk] = v.x;
        sNbrT[(c4 + 1) * SROW + kk] = v.y;
        sNbrT[(c4 + 2) * SROW + kk] = v.z;
        sNbrT[(c4 + 3) * SROW + kk] = v.w;
        const float* xnp = sXn + (kk >> 4) * 64 + c4;
        sY2[(64 + c4 + 0) * SROW + kk] = xnp[0];
        sY2[(64 + c4 + 1) * SROW + kk] = xnp[1];
        sY2[(64 + c4 + 2) * SROW + kk] = xnp[2];
        sY2[(64 + c4 + 3) * SROW + kk] = xnp[3];
    }

    // ---- x-part of GEMM1: sXh[p][c] = b1[c] + xn[p] . W1p[:,c] -----------
    {
        const int c0 = t;                   // 0..127
        float a00 = 0.f, a01 = 0.f, a10 = 0.f, a11 = 0.f;
#pragma unroll 8
        for (int j = 0; j < 64; ++j) {
            const float w0 = g_W1p[j * 256 + c0];
            const float w1 = g_W1p[j * 256 + c0 + 128];
            const float x0 = sXn[j];
            const float x1 = sXn[64 + j];
            a00 = __fmaf_rn(x0, w0, a00);
            a01 = __fmaf_rn(x0, w1, a01);
            a10 = __fmaf_rn(x1, w0, a10);
            a11 = __fmaf_rn(x1, w1, a11);
        }
        const float bb0 = b1[c0];
        const float bb1 = b1[c0 + 128];
        sXh[c0] = a00 + bb0;
        sXh[c0 + 128] = a01 + bb1;
        sXh[256 + c0] = a10 + bb0;
        sXh[256 + c0 + 128] = a11 + bb1;
    }
    __syncthreads();

    // ---- GEMM1 (nbr part): h1[c][kk] = relu(sXh + nbrT^T @ W1n) ----------
    // thread: 8 cols x 8 k (k-pairs packed in f32x2 accumulators)
    {
        const int cg = t >> 2;              // 0..31 -> cols cg*8..cg*8+7
        const int kg = t & 3;               // 0..3  -> k kg*8..kg*8+7
        const int kk0 = kg << 3;
        const int p = kg >> 1;
        ull acc[8][4];
#pragma unroll
        for (int c = 0; c < 8; ++c)
#pragma unroll
            for (int kp = 0; kp < 4; ++kp) acc[c][kp] = 0ull;

        const float* wb = g_W1n + cg * 8;
        const float* ab = sNbrT + kk0;
#pragma unroll 4
        for (int j = 0; j < 64; ++j) {
            const float4 w0 = *(const float4*)(wb + j * 256);
            const float4 w1 = *(const float4*)(wb + j * 256 + 4);
            ull wp[8];
            wp[0] = pack2(w0.x, w0.x); wp[1] = pack2(w0.y, w0.y);
            wp[2] = pack2(w0.z, w0.z); wp[3] = pack2(w0.w, w0.w);
            wp[4] = pack2(w1.x, w1.x); wp[5] = pack2(w1.y, w1.y);
            wp[6] = pack2(w1.z, w1.z); wp[7] = pack2(w1.w, w1.w);
            const ulonglong2 a01 = *(const ulonglong2*)(ab + j * SROW);
            const ulonglong2 a23 = *(const ulonglong2*)(ab + j * SROW + 4);
#pragma unroll
            for (int c = 0; c < 8; ++c) {
                acc[c][0] = fma2(a01.x, wp[c], acc[c][0]);
                acc[c][1] = fma2(a01.y, wp[c], acc[c][1]);
                acc[c][2] = fma2(a23.x, wp[c], acc[c][2]);
                acc[c][3] = fma2(a23.y, wp[c], acc[c][3]);
            }
        }
#pragma unroll
        for (int c = 0; c < 8; ++c) {
            const int ce = cg * 8 + c;
            const float xhv = sXh[p * 256 + ce];
            const float2 u0 = unpack2(acc[c][0]);
            const float2 u1 = unpack2(acc[c][1]);
            const float2 u2 = unpack2(acc[c][2]);
            const float2 u3 = unpack2(acc[c][3]);
            float4 r0, r1;
            r0.x = fmaxf(u0.x + xhv, 0.f); r0.y = fmaxf(u0.y + xhv, 0.f);
            r0.z = fmaxf(u1.x + xhv, 0.f); r0.w = fmaxf(u1.y + xhv, 0.f);
            r1.x = fmaxf(u2.x + xhv, 0.f); r1.y = fmaxf(u2.y + xhv, 0.f);
            r1.z = fmaxf(u3.x + xhv, 0.f); r1.w = fmaxf(u3.y + xhv, 0.f);
            *(float4*)(sH1 + ce * SROW + kk0) = r0;
            *(float4*)(sH1 + ce * SROW + kk0 + 4) = r1;
        }
    }
    __syncthreads();

    const int cpair = t & 15;           // channel pair -> channels 2cp, 2cp+1
    const int kq = t >> 4;              // 0..7 -> 4 k each
    const int kk0 = kq << 2;

    // ---- GEMM2: h = relu(h1^T @ W2 + b2) -> sY2 rows 32..63 ---------------
    // (2c x 4k) tile: per j one LDG.64 (weights) + one LDS.128 (acts)
    {
        ull a00 = 0ull, a01 = 0ull, a10 = 0ull, a11 = 0ull;
#pragma unroll 4
        for (int j = 0; j < 256; ++j) {
            const float2 w = *(const float2*)(W2 + (j << 5) + 2 * cpair);
            const ull wx = pack2(w.x, w.x);
            const ull wy = pack2(w.y, w.y);
            const ulonglong2 av = *(const ulonglong2*)(sH1 + j * SROW + kk0);
            a00 = fma2(av.x, wx, a00);
            a01 = fma2(av.y, wx, a01);
            a10 = fma2(av.x, wy, a10);
            a11 = fma2(av.y, wy, a11);
        }
        const float bbx = b2[2 * cpair];
        const float bby = b2[2 * cpair + 1];
        const float2 u00 = unpack2(a00), u01 = unpack2(a01);
        const float2 u10 = unpack2(a10), u11 = unpack2(a11);
        float4 r0, r1;
        r0.x = fmaxf(u00.x + bbx, 0.f); r0.y = fmaxf(u00.y + bbx, 0.f);
        r0.z = fmaxf(u01.x + bbx, 0.f); r0.w = fmaxf(u01.y + bbx, 0.f);
        r1.x = fmaxf(u10.x + bby, 0.f); r1.y = fmaxf(u10.y + bby, 0.f);
        r1.z = fmaxf(u11.x + bby, 0.f); r1.w = fmaxf(u11.y + bby, 0.f);
        *(float4*)(sY2 + (32 + 2 * cpair) * SROW + kk0) = r0;
        *(float4*)(sY2 + (33 + 2 * cpair) * SROW + kk0) = r1;
    }
    __syncthreads();

    // ---- mid: m = relu([h, xn] @ Wmid + bmid) -> sY2 rows 0..31 ------------
    {
        ull a00 = 0ull, a01 = 0ull, a10 = 0ull, a11 = 0ull;
#pragma unroll 4
        for (int j = 0; j < 96; ++j) {
            const float2 w = *(const float2*)(Wmid + (j << 5) + 2 * cpair);
            const ull wx = pack2(w.x, w.x);
            const ull wy = pack2(w.y, w.y);
            const ulonglong2 av = *(const ulonglong2*)(sY2 + (32 + j) * SROW + kk0);
            a00 = fma2(av.x, wx, a00);
            a01 = fma2(av.y, wx, a01);
            a10 = fma2(av.x, wy, a10);
            a11 = fma2(av.y, wy, a11);
        }
        const float bbx = bmid[2 * cpair];
        const float bby = bmid[2 * cpair + 1];
        const float2 u00 = unpack2(a00), u01 = unpack2(a01);
        const float2 u10 = unpack2(a10), u11 = unpack2(a11);
        float4 r0, r1;
        r0.x = fmaxf(u00.x + bbx, 0.f); r0.y = fmaxf(u00.y + bbx, 0.f);
        r0.z = fmaxf(u01.x + bbx, 0.f); r0.w = fmaxf(u01.y + bbx, 0.f);
        r1.x = fmaxf(u10.x + bby, 0.f); r1.y = fmaxf(u10.y + bby, 0.f);
        r1.z = fmaxf(u11.x + bby, 0.f); r1.w = fmaxf(u11.y + bby, 0.f);
        *(float4*)(sY2 + (2 * cpair) * SROW + kk0) = r0;
        *(float4*)(sY2 + (2 * cpair + 1) * SROW + kk0) = r1;
    }
    __syncthreads();

    // ---- ybar = mean_k y2 (thread = channel jj, loop over points) ---------
    {
        const int jj = t;
#pragma unroll
        for (int pp = 0; pp < 2; ++pp) {
            const float* row = sY2 + jj * SROW + pp * 16;
            const float4 s0 = *(const float4*)(row + 0);
            const float4 s1 = *(const float4*)(row + 4);
            const float4 s2 = *(const float4*)(row + 8);
            const float4 s3 = *(const float4*)(row + 12);
            const float s = (s0.x + s0.y + s0.z + s0.w) + (s1.x + s1.y + s1.z + s1.w)
                          + (s2.x + s2.y + s2.z + s2.w) + (s3.x + s3.y + s3.z + s3.w);
            sYbar[pp * 128 + jj] = s * (1.0f / 16.0f);
        }
    }
    __syncthreads();

    // ---- gate = sigmoid(ybar @ Wg + bg); weight shared across points ------
    {
        const int jj = t;
        float a0 = 0.f, a1 = 0.f;
#pragma unroll 4
        for (int j = 0; j < 128; ++j) {
            const float w = Wg[j * 128 + jj];
            a0 = __fmaf_rn(sYbar[j], w, a0);
            a1 = __fmaf_rn(sYbar[128 + j], w, a1);
        }
        const float bb = bg[jj];
        sGate[jj] = 1.0f / (1.0f + expf(-(a0 + bb)));
        sGate[128 + jj] = 1.0f / (1.0f + expf(-(a1 + bb)));
    }
    __syncthreads();

    // ---- y2 *= gate; out channels 32..159 = max_k ---------------------------
    {
        const int jj = t;
#pragma unroll
        for (int pp = 0; pp < 2; ++pp) {
            const float gv = sGate[pp * 128 + jj];
            float* row = sY2 + jj * SROW + pp * 16;
            float mx = -3.0e38f;
#pragma unroll
            for (int q = 0; q < 4; ++q) {
                float4 v = *(const float4*)(row + 4 * q);
                v.x *= gv; v.y *= gv; v.z *= gv; v.w *= gv;
                mx = fmaxf(mx, fmaxf(fmaxf(v.x, v.y), fmaxf(v.z, v.w)));
                *(float4*)(row + 4 * q) = v;
            }
            out[(g0 + pp) * 160 + 32 + jj] = mx;
        }
    }
    __syncthreads();

    // ---- last: out channels 0..31 = max_k (y3 @ Wlast + blast) -------------
    {
        ull a00 = 0ull, a01 = 0ull, a10 = 0ull, a11 = 0ull;
#pragma unroll 4
        for (int j = 0; j < 128; ++j) {
            const float2 w = *(const float2*)(Wlast + (j << 5) + 2 * cpair);
            const ull wx = pack2(w.x, w.x);
            const ull wy = pack2(w.y, w.y);
            const ulonglong2 av = *(const ulonglong2*)(sY2 + j * SROW + kk0);
            a00 = fma2(av.x, wx, a00);
            a01 = fma2(av.y, wx, a01);
            a10 = fma2(av.x, wy, a10);
            a11 = fma2(av.y, wy, a11);
        }
        const float bbx = blast[2 * cpair];
        const float bby = blast[2 * cpair + 1];
        const float2 u00 = unpack2(a00), u01 = unpack2(a01);
        const float2 u10 = unpack2(a10), u11 = unpack2(a11);
        const float mx0 = fmaxf(fmaxf(u00.x + bbx, u00.y + bbx),
                                fmaxf(u01.x + bbx, u01.y + bbx));
        const float mx1 = fmaxf(fmaxf(u10.x + bby, u10.y + bby),
                                fmaxf(u11.x + bby, u11.y + bby));
        sYbar[kq * 32 + 2 * cpair] = mx0;       // reuse sYbar as reduce scratch
        sYbar[kq * 32 + 2 * cpair + 1] = mx1;
    }
    __syncthreads();
    if (t < 64) {
        const int p = t >> 5;           // 0..1
        const int cc = t & 31;
        float mx = sYbar[(4 * p + 0) * 32 + cc];
        mx = fmaxf(mx, sYbar[(4 * p + 1) * 32 + cc]);
        mx = fmaxf(mx, sYbar[(4 * p + 2) * 32 + cc]);
        mx = fmaxf(mx, sYbar[(4 * p + 3) * 32 + cc]);
        out[(g0 + p) * 160 + cc] = mx;
    }
}

// ---------------------------------------------------------------------------
extern "C" void kernel_launch(void* const* d_in, const int* in_sizes, int n_in,
                              void* d_out, int out_size) {
    const float* x = (const float*)d_in[0];
    const float* pos = (const float*)d_in[1];
    const float* W1 = (const float*)d_in[2];
    const float* b1 = (const float*)d_in[3];
    const float* W2 = (const float*)d_in[4];
    const float* b2 = (const float*)d_in[5];
    const float* Wmid = (const float*)d_in[6];
    const float* bmid = (const float*)d_in[7];
    const float* Wg = (const float*)d_in[8];
    const float* bg = (const float*)d_in[9];
    const float* Wlast = (const float*)d_in[10];
    const float* blast = (const float*)d_in[11];
    float* out = (float*)d_out;

    const int smem_bytes = SMEM_FLOATS * 4;
    cudaFuncSetAttribute(conv_kernel, cudaFuncAttributeMaxDynamicSharedMemorySize,
                         smem_bytes);

    knn_prep_kernel<<<256 + 128, 128>>>(pos, W1);
    conv_kernel<<<(Bb * Nn) / P2, 128, smem_bytes>>>(
        x, b1, W2, b2, Wmid, bmid, Wg, bg, Wlast, blast, out);
}

// round 7
// speedup vs baseline: 1.2739x; 1.2739x over previous
#include <cuda_runtime.h>
#include <cuda_bf16.h>

#define Bb 8
#define Nn 4096
#define Dd 64
#define Gg 32
#define Kk 16

typedef unsigned long long ull;

// scratch
__device__ int g_nbr[Bb * Nn * Kk];
__device__ float g_W1p[64 * 256];   // W1[0:64] - W1[128:192]   (x part)
__device__ float g_W1n[64 * 256];   // W1[64:128] + W1[128:192] (nbr part)

// ---------------------------------------------------------------------------
// f32x2 packed helpers
// ---------------------------------------------------------------------------
__device__ __forceinline__ ull pack2(float a, float b) {
    ull r;
    asm("mov.b64 %0, {%1, %2};" : "=l"(r) : "f"(a), "f"(b));
    return r;
}
__device__ __forceinline__ ull fma2(ull a, ull b, ull c) {
    ull d;
    asm("fma.rn.f32x2 %0, %1, %2, %3;" : "=l"(d) : "l"(a), "l"(b), "l"(c));
    return d;
}
__device__ __forceinline__ float2 unpack2(ull v) {
    float2 f;
    asm("mov.b64 {%0, %1}, %2;" : "=f"(f.x), "=f"(f.y) : "l"(v));
    return f;
}

// ---------------------------------------------------------------------------
// Kernel 1: KNN (blocks 0..255, scalar — reverted to the fast R4 version)
// + W1 fold (blocks 256..383).
// ---------------------------------------------------------------------------
__global__ __launch_bounds__(128) void knn_prep_kernel(const float* __restrict__ pos,
                                                       const float* __restrict__ W1) {
    const int bx = blockIdx.x;
    if (bx >= 256) {
        const int i = (bx - 256) * 128 + threadIdx.x;   // 0..16383
        const int j = i >> 8;
        const int c = i & 255;
        const float wa = W1[j * 256 + c];
        const float wb = W1[(64 + j) * 256 + c];
        const float wc = W1[(128 + j) * 256 + c];
        g_W1p[i] = wa - wc;
        g_W1n[i] = wb + wc;
        return;
    }

    const int b = bx >> 5;
    const int n = ((bx & 31) << 7) + threadIdx.x;

    const float qx = pos[(b * Nn + n) * 3 + 0];
    const float qy = pos[(b * Nn + n) * 3 + 1];
    const float qz = pos[(b * Nn + n) * 3 + 2];
    const float sqn = __fadd_rn(__fadd_rn(__fmul_rn(qx, qx), __fmul_rn(qy, qy)),
                                __fmul_rn(qz, qz));

    float bd[16];
    int bi[16];
#pragma unroll
    for (int j = 0; j < 16; ++j) { bd[j] = 3.0e38f; bi[j] = 0; }
    float worst = 3.0e38f;
    int wslot = 0;

    __shared__ float4 tile[1024];

    for (int t0 = 0; t0 < Nn; t0 += 1024) {
        __syncthreads();
        for (int i = threadIdx.x; i < 1024; i += 128) {
            const float px = pos[(b * Nn + t0 + i) * 3 + 0];
            const float py = pos[(b * Nn + t0 + i) * 3 + 1];
            const float pz = pos[(b * Nn + t0 + i) * 3 + 2];
            const float sq = __fadd_rn(__fadd_rn(__fmul_rn(px, px), __fmul_rn(py, py)),
                                       __fmul_rn(pz, pz));
            tile[i] = make_float4(px, py, pz, sq);
        }
        __syncthreads();
#pragma unroll 4
        for (int i = 0; i < 1024; ++i) {
            const float4 c = tile[i];
            const int m = t0 + i;
            float dot = __fmaf_rn(qx, c.x, 0.f);
            dot = __fmaf_rn(qy, c.y, dot);
            dot = __fmaf_rn(qz, c.z, dot);
            const float dist = __fsub_rn(__fadd_rn(sqn, c.w), __fmul_rn(2.0f, dot));
            if (dist < worst && m != n) {
#pragma unroll
                for (int j = 0; j < 16; ++j)
                    if (j == wslot) { bd[j] = dist; bi[j] = m; }
                worst = bd[0]; wslot = 0;
#pragma unroll
                for (int j = 1; j < 16; ++j)
                    if (bd[j] > worst) { worst = bd[j]; wslot = j; }
            }
        }
    }

#pragma unroll
    for (int j = 0; j < 16; ++j)
        g_nbr[(b * Nn + n) * 16 + j] = bi[j];
}

// ---------------------------------------------------------------------------
// Kernel 2: fused DenseEdgeConv. 2 points (32 k-lanes), 128 threads.
// GEMM1/GEMM2 split into two 128-column halves reusing one half-size h1
// buffer -> smem ~50.8KB -> 4 CTAs/SM.
// ---------------------------------------------------------------------------
#define SROW 36
#define P2 2

#define OFF_NBRT 0
#define OFF_H1   (OFF_NBRT + 64 * SROW)         // half h1: [128 c][SROW k]
#define OFF_Y2   (OFF_H1 + 128 * SROW)
#define OFF_XH   (OFF_Y2 + 128 * SROW)
#define OFF_XN   (OFF_XH + P2 * 256)
#define OFF_YBAR (OFF_XN + P2 * 64)
#define OFF_GATE (OFF_YBAR + P2 * 128)
#define OFF_NID  (OFF_GATE + P2 * 128)
#define SMEM_FLOATS (OFF_NID + 32)

__global__ __launch_bounds__(128, 4) void conv_kernel(
    const float* __restrict__ x,
    const float* __restrict__ b1,
    const float* __restrict__ W2, const float* __restrict__ b2,
    const float* __restrict__ Wmid, const float* __restrict__ bmid,
    const float* __restrict__ Wg, const float* __restrict__ bg,
    const float* __restrict__ Wlast, const float* __restrict__ blast,
    float* __restrict__ out)
{
    extern __shared__ float sm[];
    float* sNbrT = sm + OFF_NBRT;   // [64 j][SROW k]
    float* sH1 = sm + OFF_H1;       // [128 c][SROW k] (one half at a time)
    float* sY2 = sm + OFF_Y2;       // [128 ch][SROW k]: 0..31 m, 32..63 h, 64..127 xn
    float* sXh = sm + OFF_XH;       // [2 p][256 c]
    float* sXn = sm + OFF_XN;       // [2 p][64 c]
    float* sYbar = sm + OFF_YBAR;   // [2 p][128]
    float* sGate = sm + OFF_GATE;   // [2 p][128]
    int* sNid = (int*)(sm + OFF_NID);

    const int t = threadIdx.x;
    const int g0 = blockIdx.x * P2;
    const int b = g0 >> 12;

    sXn[t] = x[(g0 + (t >> 6)) * 64 + (t & 63)];
    if (t < 32) sNid[t] = g_nbr[g0 * 16 + t];
    __syncthreads();

    // ---- gather neighbor features (transposed, LDG.128) + xn rows of y2 ---
#pragma unroll
    for (int it = 0; it < 4; ++it) {
        const int idx = it * 128 + t;       // 0..511
        const int kk = idx >> 4;            // 0..31
        const int c4 = (idx & 15) << 2;     // 0,4,...,60
        const float4 v = *(const float4*)(x + (b * Nn + sNid[kk]) * 64 + c4);
        sNbrT[(c4 + 0) * SROW + kk] = v.x;
        sNbrT[(c4 + 1) * SROW + kk] = v.y;
        sNbrT[(c4 + 2) * SROW + kk] = v.z;
        sNbrT[(c4 + 3) * SROW + kk] = v.w;
        const float* xnp = sXn + (kk >> 4) * 64 + c4;
        sY2[(64 + c4 + 0) * SROW + kk] = xnp[0];
        sY2[(64 + c4 + 1) * SROW + kk] = xnp[1];
        sY2[(64 + c4 + 2) * SROW + kk] = xnp[2];
        sY2[(64 + c4 + 3) * SROW + kk] = xnp[3];
    }

    // ---- x-part of GEMM1: sXh[p][c] = b1[c] + xn[p] . W1p[:,c] -----------
    {
        const int c0 = t;                   // 0..127
        float a00 = 0.f, a01 = 0.f, a10 = 0.f, a11 = 0.f;
#pragma unroll 8
        for (int j = 0; j < 64; ++j) {
            const float w0 = g_W1p[j * 256 + c0];
            const float w1 = g_W1p[j * 256 + c0 + 128];
            const float x0 = sXn[j];
            const float x1 = sXn[64 + j];
            a00 = __fmaf_rn(x0, w0, a00);
            a01 = __fmaf_rn(x0, w1, a01);
            a10 = __fmaf_rn(x1, w0, a10);
            a11 = __fmaf_rn(x1, w1, a11);
        }
        const float bb0 = b1[c0];
        const float bb1 = b1[c0 + 128];
        sXh[c0] = a00 + bb0;
        sXh[c0 + 128] = a01 + bb1;
        sXh[256 + c0] = a10 + bb0;
        sXh[256 + c0 + 128] = a11 + bb1;
    }
    __syncthreads();

    // ---- GEMM1 + GEMM2 in two 128-column halves ---------------------------
    // GEMM2 accumulators persist across halves (j order 0..255 preserved).
    const int cpair = t & 15;           // GEMM2 tile: channels 2cp, 2cp+1
    const int kq2 = t >> 4;             // 0..7 -> 4 k each
    const int kk2 = kq2 << 2;
    ull g2a00 = 0ull, g2a01 = 0ull, g2a10 = 0ull, g2a11 = 0ull;

#pragma unroll
    for (int h = 0; h < 2; ++h) {
        // GEMM1 half: h1[ch][kk] = relu(sXh[ch] + nbrT^T @ W1n[:,ch]),
        // ch = h*128 + 0..127. Thread: 4 cols x 8 k.
        {
            const int cg = t >> 2;          // 0..31 -> 4 cols each
            const int kg = t & 3;           // 0..3  -> 8 k each
            const int kk0 = kg << 3;
            const int p = kg >> 1;
            const int ch0 = h * 128 + cg * 4;
            ull acc[4][4];
#pragma unroll
            for (int c = 0; c < 4; ++c)
#pragma unroll
                for (int kp = 0; kp < 4; ++kp) acc[c][kp] = 0ull;

            const float* wb = g_W1n + ch0;
            const float* ab = sNbrT + kk0;
#pragma unroll 4
            for (int j = 0; j < 64; ++j) {
                const float4 w0 = *(const float4*)(wb + j * 256);
                ull wp[4];
                wp[0] = pack2(w0.x, w0.x); wp[1] = pack2(w0.y, w0.y);
                wp[2] = pack2(w0.z, w0.z); wp[3] = pack2(w0.w, w0.w);
                const ulonglong2 a01 = *(const ulonglong2*)(ab + j * SROW);
                const ulonglong2 a23 = *(const ulonglong2*)(ab + j * SROW + 4);
#pragma unroll
                for (int c = 0; c < 4; ++c) {
                    acc[c][0] = fma2(a01.x, wp[c], acc[c][0]);
                    acc[c][1] = fma2(a01.y, wp[c], acc[c][1]);
                    acc[c][2] = fma2(a23.x, wp[c], acc[c][2]);
                    acc[c][3] = fma2(a23.y, wp[c], acc[c][3]);
                }
            }
#pragma unroll
            for (int c = 0; c < 4; ++c) {
                const int ce = ch0 + c;             // global column
                const int cl = cg * 4 + c;          // local row in sH1
                const float xhv = sXh[p * 256 + ce];
                const float2 u0 = unpack2(acc[c][0]);
                const float2 u1 = unpack2(acc[c][1]);
                const float2 u2 = unpack2(acc[c][2]);
                const float2 u3 = unpack2(acc[c][3]);
                float4 r0, r1;
                r0.x = fmaxf(u0.x + xhv, 0.f); r0.y = fmaxf(u0.y + xhv, 0.f);
                r0.z = fmaxf(u1.x + xhv, 0.f); r0.w = fmaxf(u1.y + xhv, 0.f);
                r1.x = fmaxf(u2.x + xhv, 0.f); r1.y = fmaxf(u2.y + xhv, 0.f);
                r1.z = fmaxf(u3.x + xhv, 0.f); r1.w = fmaxf(u3.y + xhv, 0.f);
                *(float4*)(sH1 + cl * SROW + kk0) = r0;
                *(float4*)(sH1 + cl * SROW + kk0 + 4) = r1;
            }
        }
        __syncthreads();

        // GEMM2 partial: j = h*128 .. h*128+127
        {
            const float* w2p = W2 + (h << 12) + 2 * cpair;  // h*128*32
#pragma unroll 4
            for (int j = 0; j < 128; ++j) {
                const float2 w = *(const float2*)(w2p + (j << 5));
                const ull wx = pack2(w.x, w.x);
                const ull wy = pack2(w.y, w.y);
                const ulonglong2 av = *(const ulonglong2*)(sH1 + j * SROW + kk2);
                g2a00 = fma2(av.x, wx, g2a00);
                g2a01 = fma2(av.y, wx, g2a01);
                g2a10 = fma2(av.x, wy, g2a10);
                g2a11 = fma2(av.y, wy, g2a11);
            }
        }
        __syncthreads();
    }

    // ---- GEMM2 epilogue -> sY2 rows 32..63 --------------------------------
    {
        const float bbx = b2[2 * cpair];
        const float bby = b2[2 * cpair + 1];
        const float2 u00 = unpack2(g2a00), u01 = unpack2(g2a01);
        const float2 u10 = unpack2(g2a10), u11 = unpack2(g2a11);
        float4 r0, r1;
        r0.x = fmaxf(u00.x + bbx, 0.f); r0.y = fmaxf(u00.y + bbx, 0.f);
        r0.z = fmaxf(u01.x + bbx, 0.f); r0.w = fmaxf(u01.y + bbx, 0.f);
        r1.x = fmaxf(u10.x + bby, 0.f); r1.y = fmaxf(u10.y + bby, 0.f);
        r1.z = fmaxf(u11.x + bby, 0.f); r1.w = fmaxf(u11.y + bby, 0.f);
        *(float4*)(sY2 + (32 + 2 * cpair) * SROW + kk2) = r0;
        *(float4*)(sY2 + (33 + 2 * cpair) * SROW + kk2) = r1;
    }
    __syncthreads();

    // ---- mid: m = relu([h, xn] @ Wmid + bmid) -> sY2 rows 0..31 ------------
    {
        ull a00 = 0ull, a01 = 0ull, a10 = 0ull, a11 = 0ull;
#pragma unroll 4
        for (int j = 0; j < 96; ++j) {
            const float2 w = *(const float2*)(Wmid + (j << 5) + 2 * cpair);
            const ull wx = pack2(w.x, w.x);
            const ull wy = pack2(w.y, w.y);
            const ulonglong2 av = *(const ulonglong2*)(sY2 + (32 + j) * SROW + kk2);
            a00 = fma2(av.x, wx, a00);
            a01 = fma2(av.y, wx, a01);
            a10 = fma2(av.x, wy, a10);
            a11 = fma2(av.y, wy, a11);
        }
        const float bbx = bmid[2 * cpair];
        const float bby = bmid[2 * cpair + 1];
        const float2 u00 = unpack2(a00), u01 = unpack2(a01);
        const float2 u10 = unpack2(a10), u11 = unpack2(a11);
        float4 r0, r1;
        r0.x = fmaxf(u00.x + bbx, 0.f); r0.y = fmaxf(u00.y + bbx, 0.f);
        r0.z = fmaxf(u01.x + bbx, 0.f); r0.w = fmaxf(u01.y + bbx, 0.f);
        r1.x = fmaxf(u10.x + bby, 0.f); r1.y = fmaxf(u10.y + bby, 0.f);
        r1.z = fmaxf(u11.x + bby, 0.f); r1.w = fmaxf(u11.y + bby, 0.f);
        *(float4*)(sY2 + (2 * cpair) * SROW + kk2) = r0;
        *(float4*)(sY2 + (2 * cpair + 1) * SROW + kk2) = r1;
    }
    __syncthreads();

    // ---- ybar = mean_k y2 (thread = channel jj, loop over points) ---------
    {
        const int jj = t;
#pragma unroll
        for (int pp = 0; pp < 2; ++pp) {
            const float* row = sY2 + jj * SROW + pp * 16;
            const float4 s0 = *(const float4*)(row + 0);
            const float4 s1 = *(const float4*)(row + 4);
            const float4 s2 = *(const float4*)(row + 8);
            const float4 s3 = *(const float4*)(row + 12);
            const float s = (s0.x + s0.y + s0.z + s0.w) + (s1.x + s1.y + s1.z + s1.w)
                          + (s2.x + s2.y + s2.z + s2.w) + (s3.x + s3.y + s3.z + s3.w);
            sYbar[pp * 128 + jj] = s * (1.0f / 16.0f);
        }
    }
    __syncthreads();

    // ---- gate = sigmoid(ybar @ Wg + bg); weight shared across points ------
    {
        const int jj = t;
        float a0 = 0.f, a1 = 0.f;
#pragma unroll 4
        for (int j = 0; j < 128; ++j) {
            const float w = Wg[j * 128 + jj];
            a0 = __fmaf_rn(sYbar[j], w, a0);
            a1 = __fmaf_rn(sYbar[128 + j], w, a1);
        }
        const float bb = bg[jj];
        sGate[jj] = 1.0f / (1.0f + expf(-(a0 + bb)));
        sGate[128 + jj] = 1.0f / (1.0f + expf(-(a1 + bb)));
    }
    __syncthreads();

    // ---- y2 *= gate; out channels 32..159 = max_k ---------------------------
    {
        const int jj = t;
#pragma unroll
        for (int pp = 0; pp < 2; ++pp) {
            const float gv = sGate[pp * 128 + jj];
            float* row = sY2 + jj * SROW + pp * 16;
            float mx = -3.0e38f;
#pragma unroll
            for (int q = 0; q < 4; ++q) {
                float4 v = *(const float4*)(row + 4 * q);
                v.x *= gv; v.y *= gv; v.z *= gv; v.w *= gv;
                mx = fmaxf(mx, fmaxf(fmaxf(v.x, v.y), fmaxf(v.z, v.w)));
                *(float4*)(row + 4 * q) = v;
            }
            out[(g0 + pp) * 160 + 32 + jj] = mx;
        }
    }
    __syncthreads();

    // ---- last: out channels 0..31 = max_k (y3 @ Wlast + blast) -------------
    {
        ull a00 = 0ull, a01 = 0ull, a10 = 0ull, a11 = 0ull;
#pragma unroll 4
        for (int j = 0; j < 128; ++j) {
            const float2 w = *(const float2*)(Wlast + (j << 5) + 2 * cpair);
            const ull wx = pack2(w.x, w.x);
            const ull wy = pack2(w.y, w.y);
            const ulonglong2 av = *(const ulonglong2*)(sY2 + j * SROW + kk2);
            a00 = fma2(av.x, wx, a00);
            a01 = fma2(av.y, wx, a01);
            a10 = fma2(av.x, wy, a10);
            a11 = fma2(av.y, wy, a11);
        }
        const float bbx = blast[2 * cpair];
        const float bby = blast[2 * cpair + 1];
        const float2 u00 = unpack2(a00), u01 = unpack2(a01);
        const float2 u10 = unpack2(a10), u11 = unpack2(a11);
        const float mx0 = fmaxf(fmaxf(u00.x + bbx, u00.y + bbx),
                                fmaxf(u01.x + bbx, u01.y + bbx));
        const float mx1 = fmaxf(fmaxf(u10.x + bby, u10.y + bby),
                                fmaxf(u11.x + bby, u11.y + bby));
        sYbar[kq2 * 32 + 2 * cpair] = mx0;      // reuse sYbar as reduce scratch
        sYbar[kq2 * 32 + 2 * cpair + 1] = mx1;
    }
    __syncthreads();
    if (t < 64) {
        const int p = t >> 5;           // 0..1
        const int cc = t & 31;
        float mx = sYbar[(4 * p + 0) * 32 + cc];
        mx = fmaxf(mx, sYbar[(4 * p + 1) * 32 + cc]);
        mx = fmaxf(mx, sYbar[(4 * p + 2) * 32 + cc]);
        mx = fmaxf(mx, sYbar[(4 * p + 3) * 32 + cc]);
        out[(g0 + p) * 160 + cc] = mx;
    }
}

// ---------------------------------------------------------------------------
extern "C" void kernel_launch(void* const* d_in, const int* in_sizes, int n_in,
                              void* d_out, int out_size) {
    const float* x = (const float*)d_in[0];
    const float* pos = (const float*)d_in[1];
    const float* W1 = (const float*)d_in[2];
    const float* b1 = (const float*)d_in[3];
    const float* W2 = (const float*)d_in[4];
    const float* b2 = (const float*)d_in[5];
    const float* Wmid = (const float*)d_in[6];
    const float* bmid = (const float*)d_in[7];
    const float* Wg = (const float*)d_in[8];
    const float* bg = (const float*)d_in[9];
    const float* Wlast = (const float*)d_in[10];
    const float* blast = (const float*)d_in[11];
    float* out = (float*)d_out;

    const int smem_bytes = SMEM_FLOATS * 4;
    cudaFuncSetAttribute(conv_kernel, cudaFuncAttributeMaxDynamicSharedMemorySize,
                         smem_bytes);

    knn_prep_kernel<<<256 + 128, 128>>>(pos, W1);
    conv_kernel<<<(Bb * Nn) / P2, 128, smem_bytes>>>(
        x, b1, W2, b2, Wmid, bmid, Wg, bg, Wlast, blast, out);
}